// round 15
// baseline (speedup 1.0000x reference)
#include <cuda_runtime.h>
#include <cstdint>
#include <cstddef>

// ---------------- scratch (static __device__ arrays; no cudaMalloc) ----------------
static __device__ float  g_xchw[2 * 512 * 512];
static __device__ float  g_h1 [32 * 512 * 512];
static __device__ float  g_h2p[64 * 256 * 256];
static __device__ float  g_h3 [128 * 256 * 256];
static __device__ float  g_feat[128];
static __device__ float  g_f2[512];
static __device__ float  g_u1[512];
static __device__ float  g_v1[512];
static __device__ float2 g_Ut[128 * 512];      // column-contiguous: [r][m]
static __device__ float2 g_Vt[128 * 512];
static __device__ float2 g_G [2 * 128 * 128];  // FULL Gram matrices
static __device__ float2 g_W [2 * 128 * 128];  // MGS transform: Q = A * W (cols t_j)

// ---------------- (H,W,2) -> CHW transpose ----------------
__global__ void prep_x_kernel(const float* __restrict__ x, float* __restrict__ xchw) {
    int idx = blockIdx.x * 256 + threadIdx.x;   // 512*512 exactly
    float2 v = reinterpret_cast<const float2*>(x)[idx];
    xchw[idx] = v.x;
    xchw[512 * 512 + idx] = v.y;
}

// ---------------- scalar direct conv (used only for tiny conv1, CIN=2) ------------
template<int CIN>
__global__ __launch_bounds__(128)
void conv3x3_relu(const float* __restrict__ in, const float* __restrict__ wt,
                  const float* __restrict__ bias, float* __restrict__ out,
                  int H, int W) {
    extern __shared__ float sw[];               // 16 * CIN * 9 floats
    const int tid = threadIdx.x;
    const int obase = blockIdx.z * 16;
    for (int idx = tid; idx < 16 * CIN * 9; idx += 128)
        sw[idx] = wt[obase * CIN * 9 + idx];
    __syncthreads();

    const int og = tid >> 6;
    const int pg = tid & 63;
    const int h  = blockIdx.y;
    const int x0 = blockIdx.x * 256 + pg * 4;

    float acc[8][4];
#pragma unroll
    for (int a = 0; a < 8; ++a)
#pragma unroll
        for (int p = 0; p < 4; ++p) acc[a][p] = 0.f;

#pragma unroll
    for (int c = 0; c < CIN; ++c) {
#pragma unroll
        for (int ky = 0; ky < 3; ++ky) {
            const int yy = h + ky - 1;
            const bool yv = ((unsigned)yy < (unsigned)H);
            const float* ip = in + ((size_t)c * H + yy) * W;
            float r[6];
#pragma unroll
            for (int dx = 0; dx < 6; ++dx) {
                int xx = x0 - 1 + dx;
                r[dx] = (yv && (unsigned)xx < (unsigned)W) ? __ldg(ip + xx) : 0.f;
            }
            const float* swp = sw + (og * 8) * (CIN * 9) + c * 9 + ky * 3;
#pragma unroll
            for (int kx = 0; kx < 3; ++kx) {
#pragma unroll
                for (int oo = 0; oo < 8; ++oo) {
                    float wv = swp[oo * (CIN * 9) + kx];
                    acc[oo][0] = fmaf(wv, r[kx + 0], acc[oo][0]);
                    acc[oo][1] = fmaf(wv, r[kx + 1], acc[oo][1]);
                    acc[oo][2] = fmaf(wv, r[kx + 2], acc[oo][2]);
                    acc[oo][3] = fmaf(wv, r[kx + 3], acc[oo][3]);
                }
            }
        }
    }
#pragma unroll
    for (int oo = 0; oo < 8; ++oo) {
        const int o = obase + og * 8 + oo;
        const float b = bias[o];
        float4 res;
        res.x = fmaxf(acc[oo][0] + b, 0.f); res.y = fmaxf(acc[oo][1] + b, 0.f);
        res.z = fmaxf(acc[oo][2] + b, 0.f); res.w = fmaxf(acc[oo][3] + b, 0.f);
        *reinterpret_cast<float4*>(out + ((size_t)o * H + h) * W + x0) = res;
    }
}

// ---------------- tf32 helpers ----------------
__device__ __forceinline__ float tf32r(float v) {
    uint32_t r;
    asm("cvt.rna.tf32.f32 %0, %1;" : "=r"(r) : "f"(v));
    return __uint_as_float(r);
}
__device__ __forceinline__ void mma_tf32(float* c, uint32_t a0, uint32_t a1,
                                         uint32_t a2, uint32_t a3,
                                         uint32_t b0, uint32_t b1) {
    asm volatile(
        "mma.sync.aligned.m16n8k8.row.col.f32.tf32.tf32.f32 "
        "{%0,%1,%2,%3}, {%4,%5,%6,%7}, {%8,%9}, {%0,%1,%2,%3};"
        : "+f"(c[0]), "+f"(c[1]), "+f"(c[2]), "+f"(c[3])
        : "r"(a0), "r"(a1), "r"(a2), "r"(a3), "r"(b0), "r"(b1));
}
__device__ __forceinline__ uint32_t fbits(float v) { return __float_as_uint(v); }

// X smem: 4 channel-pair planes of float2 (pair = (ch tg, ch tg+4)); plane stride
// padded to ≡ 4 (mod 16) float2 -> LDS.64 B-fragment loads are bank-conflict-free.

// ---------------- conv2 (32->64) tf32 MMA, fused 2x2 maxpool ----------------
// X planes: 4 rows x 130 px = 520 pixels, plane stride 532 float2.
// floats: xh2 4*532*2=4256 | xl2 4256 | wh[64][76]=4864 | wl 4864 = 18240
#define C2P_SMEM_FLOATS 18240
#define PX2 532
__global__ __launch_bounds__(256)
void conv2_mma_pool(const float* __restrict__ in, const float* __restrict__ wt,
                    const float* __restrict__ bias, float* __restrict__ out) {
    extern __shared__ float sm[];
    float* xhF = sm;                    // float view for stores
    float* xlF = sm + 4256;
    float* wh  = sm + 8512;
    float* wl  = sm + 13376;
    const float2* xh2 = (const float2*)xhF;
    const float2* xl2 = (const float2*)xlF;

    const int t = threadIdx.x;
    const int lane = t & 31, warp = t >> 5;
    const int g = lane >> 2, tg = lane & 3;
    const int mwarp = warp & 3, nwarp = warp >> 2;
    const int x0 = blockIdx.x * 128;
    const int y0 = blockIdx.y * 2;

    float acc[2][8][4];
#pragma unroll
    for (int ry = 0; ry < 2; ++ry)
#pragma unroll
        for (int nt = 0; nt < 8; ++nt)
#pragma unroll
            for (int i = 0; i < 4; ++i) acc[ry][nt][i] = 0.f;

#pragma unroll 1
    for (int c0 = 0; c0 < 4; ++c0) {    // 32 in-ch / 8
        __syncthreads();
        // X slab: 8 ch x 4 rows x 130 px into pair planes
        for (int idx = t; idx < 4160; idx += 256) {
            int c  = idx / 520;
            int rr = idx - c * 520;                 // r*130 + x
            int r  = rr / 130, x = rr - r * 130;
            int yy = y0 + r - 1, xx = x0 + x - 1;
            float v = 0.f;
            if ((unsigned)yy < 512u && (unsigned)xx < 512u)
                v = __ldg(in + ((size_t)(c0 * 8 + c) * 512 + yy) * 512 + xx);
            float hi = tf32r(v);
            float lo = tf32r(v - hi);
            int o = ((c & 3) * PX2 + rr) * 2 + (c >> 2);
            xhF[o] = hi; xlF[o] = lo;
        }
        for (int idx = t; idx < 4608; idx += 256) {
            int o = idx / 72, r = idx - o * 72;
            int s = r >> 3, k = r & 7;
            float v = __ldg(wt + ((size_t)o * 32 + c0 * 8 + k) * 9 + s);
            float hi = tf32r(v);
            float lo = tf32r(v - hi);
            wh[o * 76 + s * 8 + k] = hi;
            wl[o * 76 + s * 8 + k] = lo;
        }
        __syncthreads();

#pragma unroll
        for (int ky = 0; ky < 3; ++ky) {
#pragma unroll
            for (int kx = 0; kx < 3; ++kx) {
                const int s = ky * 3 + kx;
                const float* pwh = wh + (mwarp * 16 + g) * 76 + s * 8 + tg;
                const float* pwl = wl + (mwarp * 16 + g) * 76 + s * 8 + tg;
                uint32_t a0h = fbits(pwh[0]),      a2h = fbits(pwh[4]);
                uint32_t a1h = fbits(pwh[8 * 76]), a3h = fbits(pwh[8 * 76 + 4]);
                uint32_t a0l = fbits(pwl[0]),      a2l = fbits(pwl[4]);
                uint32_t a1l = fbits(pwl[8 * 76]), a3l = fbits(pwl[8 * 76 + 4]);
#pragma unroll
                for (int ry = 0; ry < 2; ++ry) {
                    const int fb = tg * PX2 + (ky + ry) * 130 + nwarp * 64 + g + kx;
#pragma unroll
                    for (int nt = 0; nt < 8; ++nt) {
                        float2 bh = xh2[fb + nt * 8];
                        float2 bl = xl2[fb + nt * 8];
                        uint32_t b0h = fbits(bh.x), b1h = fbits(bh.y);
                        uint32_t b0l = fbits(bl.x), b1l = fbits(bl.y);
                        mma_tf32(acc[ry][nt], a0h, a1h, a2h, a3h, b0h, b1h);
                        mma_tf32(acc[ry][nt], a0l, a1l, a2l, a3l, b0h, b1h);
                        mma_tf32(acc[ry][nt], a0h, a1h, a2h, a3h, b0l, b1l);
                    }
                }
            }
        }
    }

    const int o_lo = mwarp * 16 + g;
    const float b_lo = __ldg(bias + o_lo);
    const float b_hi = __ldg(bias + o_lo + 8);
    float* rowp_lo = out + ((size_t)o_lo * 256 + blockIdx.y) * 256;
    float* rowp_hi = out + ((size_t)(o_lo + 8) * 256 + blockIdx.y) * 256;
#pragma unroll
    for (int nt = 0; nt < 8; ++nt) {
        int xp = x0 / 2 + nwarp * 32 + nt * 4 + tg;
        float l00 = fmaxf(acc[0][nt][0] + b_lo, 0.f), l01 = fmaxf(acc[0][nt][1] + b_lo, 0.f);
        float l10 = fmaxf(acc[1][nt][0] + b_lo, 0.f), l11 = fmaxf(acc[1][nt][1] + b_lo, 0.f);
        rowp_lo[xp] = fmaxf(fmaxf(l00, l01), fmaxf(l10, l11));
        float h00 = fmaxf(acc[0][nt][2] + b_hi, 0.f), h01 = fmaxf(acc[0][nt][3] + b_hi, 0.f);
        float h10 = fmaxf(acc[1][nt][2] + b_hi, 0.f), h11 = fmaxf(acc[1][nt][3] + b_hi, 0.f);
        rowp_hi[xp] = fmaxf(fmaxf(h00, h01), fmaxf(h10, h11));
    }
}

// ---------------- conv3 tf32 MMA ----------------
// X planes: 3 rows x 130 = 390 pixels, plane stride 404 float2.
// floats: xh2 4*404*2=3232 | xl2 3232 | wh 4864 | wl 4864 = 16192
#define CMM_SMEM_FLOATS 16192
#define PX3 404
template<int CIN>
__global__ __launch_bounds__(256)
void conv3x3_mma(const float* __restrict__ in, const float* __restrict__ wt,
                 const float* __restrict__ bias, float* __restrict__ out,
                 int H, int W) {
    extern __shared__ float sm[];
    float* xhF = sm;
    float* xlF = sm + 3232;
    float* wh  = sm + 6464;
    float* wl  = sm + 11328;
    const float2* xh2 = (const float2*)xhF;
    const float2* xl2 = (const float2*)xlF;

    const int t = threadIdx.x;
    const int lane = t & 31, warp = t >> 5;
    const int g = lane >> 2, tg = lane & 3;
    const int mwarp = warp & 3, nwarp = warp >> 2;
    const int x0 = blockIdx.x * 128;
    const int y  = blockIdx.y;
    const int obase = blockIdx.z * 64;

    float acc[8][4];
#pragma unroll
    for (int nt = 0; nt < 8; ++nt)
#pragma unroll
        for (int i = 0; i < 4; ++i) acc[nt][i] = 0.f;

#pragma unroll 1
    for (int c0 = 0; c0 < CIN / 8; ++c0) {
        __syncthreads();
        for (int idx = t; idx < 3120; idx += 256) {
            int c  = idx / 390;
            int rr = idx - c * 390;                 // r*130 + x
            int r  = rr / 130, x = rr - r * 130;
            int yy = y + r - 1, xx = x0 + x - 1;
            float v = 0.f;
            if ((unsigned)yy < (unsigned)H && (unsigned)xx < (unsigned)W)
                v = __ldg(in + ((size_t)(c0 * 8 + c) * H + yy) * W + xx);
            float hi = tf32r(v);
            float lo = tf32r(v - hi);
            int o = ((c & 3) * PX3 + rr) * 2 + (c >> 2);
            xhF[o] = hi; xlF[o] = lo;
        }
        for (int idx = t; idx < 4608; idx += 256) {
            int o = idx / 72, r = idx - o * 72;
            int s = r >> 3, k = r & 7;
            float v = __ldg(wt + ((size_t)(obase + o) * CIN + c0 * 8 + k) * 9 + s);
            float hi = tf32r(v);
            float lo = tf32r(v - hi);
            wh[o * 76 + s * 8 + k] = hi;
            wl[o * 76 + s * 8 + k] = lo;
        }
        __syncthreads();

#pragma unroll
        for (int ky = 0; ky < 3; ++ky) {
#pragma unroll
            for (int kx = 0; kx < 3; ++kx) {
                const int s = ky * 3 + kx;
                const float* pwh = wh + (mwarp * 16 + g) * 76 + s * 8 + tg;
                const float* pwl = wl + (mwarp * 16 + g) * 76 + s * 8 + tg;
                uint32_t a0h = fbits(pwh[0]),      a2h = fbits(pwh[4]);
                uint32_t a1h = fbits(pwh[8 * 76]), a3h = fbits(pwh[8 * 76 + 4]);
                uint32_t a0l = fbits(pwl[0]),      a2l = fbits(pwl[4]);
                uint32_t a1l = fbits(pwl[8 * 76]), a3l = fbits(pwl[8 * 76 + 4]);
                const int fb = tg * PX3 + ky * 130 + nwarp * 64 + g + kx;
#pragma unroll
                for (int nt = 0; nt < 8; ++nt) {
                    float2 bh = xh2[fb + nt * 8];
                    float2 bl = xl2[fb + nt * 8];
                    uint32_t b0h = fbits(bh.x), b1h = fbits(bh.y);
                    uint32_t b0l = fbits(bl.x), b1l = fbits(bl.y);
                    mma_tf32(acc[nt], a0h, a1h, a2h, a3h, b0h, b1h);
                    mma_tf32(acc[nt], a0l, a1l, a2l, a3l, b0h, b1h);
                    mma_tf32(acc[nt], a0h, a1h, a2h, a3h, b0l, b1l);
                }
            }
        }
    }

    const int o_lo = obase + mwarp * 16 + g;
    const float b_lo = __ldg(bias + o_lo);
    const float b_hi = __ldg(bias + o_lo + 8);
    float* row_lo = out + ((size_t)o_lo * H + y) * W;
    float* row_hi = out + ((size_t)(o_lo + 8) * H + y) * W;
#pragma unroll
    for (int nt = 0; nt < 8; ++nt) {
        int x = x0 + nwarp * 64 + nt * 8 + 2 * tg;
        float2 v0 = make_float2(fmaxf(acc[nt][0] + b_lo, 0.f),
                                fmaxf(acc[nt][1] + b_lo, 0.f));
        float2 v1 = make_float2(fmaxf(acc[nt][2] + b_hi, 0.f),
                                fmaxf(acc[nt][3] + b_hi, 0.f));
        *reinterpret_cast<float2*>(row_lo + x) = v0;
        *reinterpret_cast<float2*>(row_hi + x) = v1;
    }
}

// ---------------- global average pool: 128 channels of 256x256 ----------------
__global__ void avgpool_kernel(const float* __restrict__ in, float* __restrict__ feat) {
    const int c = blockIdx.x;
    const float* p = in + (size_t)c * 65536;
    float s = 0.f;
    for (int i = threadIdx.x; i < 65536; i += 256) s += p[i];
    __shared__ float sh[256];
    sh[threadIdx.x] = s;
    __syncthreads();
    for (int off = 128; off > 0; off >>= 1) {
        if (threadIdx.x < off) sh[threadIdx.x] += sh[threadIdx.x + off];
        __syncthreads();
    }
    if (threadIdx.x == 0) feat[c] = sh[0] * (1.f / 65536.f);
}

// ---------------- fused small FC trunk + s head (softplus+sort); exports f2 ----------
__device__ __forceinline__ float dot4(const float* __restrict__ w,
                                      const float* __restrict__ v, int n4) {
    float a = 0.f;
    const float4* w4 = (const float4*)w;
    const float4* v4 = (const float4*)v;
#pragma unroll 8
    for (int k = 0; k < n4; ++k) {
        float4 ww = w4[k], vv = v4[k];
        a += ww.x * vv.x + ww.y * vv.y + ww.z * vv.z + ww.w * vv.w;
    }
    return a;
}

__global__ __launch_bounds__(512)
void small_layers_kernel(const float* __restrict__ feat,
    const float* __restrict__ fw1, const float* __restrict__ fb1,
    const float* __restrict__ fw2, const float* __restrict__ fb2,
    const float* __restrict__ sw1, const float* __restrict__ sb1,
    const float* __restrict__ sw2, const float* __restrict__ sb2,
    float* __restrict__ f2g, float* __restrict__ s_out) {
    __shared__ __align__(16) float sf[128];
    __shared__ __align__(16) float f1[256];
    __shared__ __align__(16) float f2[512];
    __shared__ __align__(16) float s1[256];
    __shared__ float sv[128];
    const int t = threadIdx.x;

    if (t < 128) sf[t] = feat[t];
    __syncthreads();

    if (t < 256) f1[t] = fmaxf(fb1[t] + dot4(fw1 + t * 128, sf, 32), 0.f);
    __syncthreads();

    {
        float val = fmaxf(fb2[t] + dot4(fw2 + t * 256, f1, 64), 0.f);
        f2[t] = val;
        f2g[t] = val;
    }
    __syncthreads();

    if (t < 256) s1[t] = fmaxf(sb1[t] + dot4(sw1 + (size_t)t * 512, f2, 128), 0.f);
    __syncthreads();

    if (t < 128) {
        float xv = sb2[t] + dot4(sw2 + t * 256, s1, 64);
        sv[t] = (xv > 0.f) ? (xv + log1pf(expf(-xv))) : log1pf(expf(xv));
    }
    __syncthreads();

    if (t < 128) {
        float v = sv[t];
        int rank = 0;
        for (int j = 0; j < 128; ++j) {
            float o = sv[j];
            rank += (o > v) || (o == v && j > t);
        }
        s_out[rank] = v;
    }
}

// ---------------- u1/v1 matvecs in parallel (1024 warps) ----------------
__global__ __launch_bounds__(256)
void u1v1_kernel(const float* __restrict__ uw1, const float* __restrict__ ub1,
                 const float* __restrict__ vw1, const float* __restrict__ vb1,
                 const float* __restrict__ f2g,
                 float* __restrict__ u1, float* __restrict__ v1) {
    __shared__ __align__(16) float sf[512];
    const int t = threadIdx.x;
    sf[t] = f2g[t]; sf[t + 256] = f2g[t + 256];
    __syncthreads();
    const int lane = t & 31, warp = t >> 5;
    const int row = blockIdx.x * 8 + warp;          // 0..1023
    const float* wrow;
    float b; float* dst;
    if (row < 512) { wrow = uw1 + (size_t)row * 512; b = ub1[row]; dst = u1 + row; }
    else { wrow = vw1 + (size_t)(row - 512) * 512; b = vb1[row - 512]; dst = v1 + (row - 512); }
    float a = 0.f;
    const float4* w4 = (const float4*)wrow;
    const float4* x4 = (const float4*)sf;
#pragma unroll
    for (int k = lane; k < 128; k += 32) {
        float4 ww = w4[k], vv = x4[k];
        a += ww.x * vv.x + ww.y * vv.y + ww.z * vv.z + ww.w * vv.w;
    }
#pragma unroll
    for (int off = 16; off; off >>= 1) a += __shfl_down_sync(0xffffffffu, a, off);
    if (lane == 0) *dst = fmaxf(a + b, 0.f);
}

// ---------------- big head matvecs: 2 x (131072 x 512), write transposed ----------------
__global__ __launch_bounds__(256)
void big_head_kernel(const float* __restrict__ uw2, const float* __restrict__ ub2,
                     const float* __restrict__ vw2, const float* __restrict__ vb2,
                     const float* __restrict__ u1, const float* __restrict__ v1,
                     float* __restrict__ Ut, float* __restrict__ Vt) {
    __shared__ __align__(16) float su[512];
    __shared__ __align__(16) float svv[512];
    const int t = threadIdx.x;
    for (int i = t; i < 512; i += 256) { su[i] = u1[i]; svv[i] = v1[i]; }
    __syncthreads();

    const int lane = t & 31, warp = t >> 5;
    const int gw = blockIdx.x * 8 + warp;
#pragma unroll 1
    for (int rr = 0; rr < 16; ++rr) {
        int e = gw * 16 + rr;
        const float* wrow; const float* xv; float b; float* dst;
        if (e < 131072) {
            wrow = uw2 + (size_t)e * 512; xv = su; b = ub2[e];
            int m = e >> 8, r = (e >> 1) & 127, cp = e & 1;
            dst = Ut + (size_t)(r * 512 + m) * 2 + cp;
        } else {
            int e2 = e - 131072;
            wrow = vw2 + (size_t)e2 * 512; xv = svv; b = vb2[e2];
            int m = e2 >> 8, r = (e2 >> 1) & 127, cp = e2 & 1;
            dst = Vt + (size_t)(r * 512 + m) * 2 + cp;
        }
        float a = 0.f;
        const float4* w4 = (const float4*)wrow;
        const float4* x4 = (const float4*)xv;
#pragma unroll
        for (int k = lane; k < 128; k += 32) {
            float4 ww = w4[k], vv = x4[k];
            a += ww.x * vv.x + ww.y * vv.y + ww.z * vv.z + ww.w * vv.w;
        }
#pragma unroll
        for (int off = 16; off; off >>= 1) a += __shfl_down_sync(0xffffffffu, a, off);
        if (lane == 0) *dst = a + b;
    }
}

// ---------------- Gram: G = A^H A (FULL matrix) ------------------------------------
__global__ __launch_bounds__(256)
void gram_kernel(const float2* __restrict__ A0, const float2* __restrict__ A1,
                 float2* __restrict__ G) {
    const float2* A = (blockIdx.y == 0) ? A0 : A1;
    float2* Gm = G + blockIdx.y * 128 * 128;
    const int p = blockIdx.x;
    const int lane = threadIdx.x & 31, warp = threadIdx.x >> 5;
    const float2* ap = A + (size_t)p * 512;
    for (int q = warp; q < 128; q += 8) {
        const float2* aq = A + (size_t)q * 512;
        float cr = 0.f, ci = 0.f;
#pragma unroll
        for (int k = 0; k < 16; ++k) {
            float2 xp = ap[lane + 32 * k], xq = aq[lane + 32 * k];
            cr += xp.x * xq.x + xp.y * xq.y;    // re(conj(a_p) . a_q)
            ci += xp.x * xq.y - xp.y * xq.x;    // im
        }
#pragma unroll
        for (int off = 16; off; off >>= 1) {
            cr += __shfl_xor_sync(0xffffffffu, cr, off);
            ci += __shfl_xor_sync(0xffffffffu, ci, off);
        }
        if (lane == 0) Gm[p * 128 + q] = make_float2(cr, ci);
    }
}

// ---------------- Gram-space MGS with eps (EXACT reference semantics) --------------
#define GSG_SMEM_BYTES (128 * 130 * 8 + 2 * 128 * 8)
__global__ __launch_bounds__(1024, 1)
void gsgram_kernel(const float2* __restrict__ G, float2* __restrict__ gW) {
    extern __shared__ float2 sm2[];
    float2* sU  = sm2;                 // [col][row], col stride 130
    float2* sT  = sm2 + 128 * 130;     // t_i broadcast
    float2* sGT = sT + 128;            // (G t_i) broadcast
    const float2* Gm = G + blockIdx.x * 128 * 128;
    float2* Wm = gW + blockIdx.x * 128 * 128;
    const int t = threadIdx.x, lane = t & 31, warp = t >> 5;

    for (int idx = t; idx < 16384; idx += 1024) {
        int r = idx >> 7, j = idx & 127;
        sU[j * 130 + r] = Gm[r * 128 + j];
    }

    float2 v[4][4];                                // [colslot][rowslot]
#pragma unroll
    for (int cs = 0; cs < 4; ++cs)
#pragma unroll
        for (int rs = 0; rs < 4; ++rs) v[cs][rs] = make_float2(0.f, 0.f);
    if (lane == warp) {
#pragma unroll
        for (int cs = 0; cs < 4; ++cs) v[cs][cs] = make_float2(1.f, 0.f);
    }
    __syncthreads();

#pragma unroll 1
    for (int i = 0; i < 128; ++i) {
        const int iw = i & 31, is = i >> 5;
        if (warp == iw) {
            float d2 = 0.f;
#pragma unroll
            for (int rs = 0; rs < 4; ++rs) {
                float2 vv = v[is][rs];
                float2 uu = sU[i * 130 + lane + 32 * rs];
                d2 += vv.x * uu.x + vv.y * uu.y;
            }
#pragma unroll
            for (int off = 16; off; off >>= 1) d2 += __shfl_xor_sync(0xffffffffu, d2, off);
            const float inv = 1.f / sqrtf(d2 + 1e-8f);   // reference epsilon, exactly
#pragma unroll
            for (int rs = 0; rs < 4; ++rs) {
                int r = lane + 32 * rs;
                float2 vv = v[is][rs];
                float2 tv = make_float2(vv.x * inv, vv.y * inv);
                sT[r] = tv;
                Wm[i * 128 + r] = tv;
                float2 uu = sU[i * 130 + r];
                sGT[r] = make_float2(uu.x * inv, uu.y * inv);
            }
        }
        __syncthreads();
#pragma unroll
        for (int cs = 0; cs < 4; ++cs) {
            const int j = warp + 32 * cs;
            if (j > i) {
                float cr = 0.f, ci = 0.f;
#pragma unroll
                for (int rs = 0; rs < 4; ++rs) {
                    int r = lane + 32 * rs;
                    float2 tt = sT[r];
                    float2 uu = sU[j * 130 + r];
                    cr += tt.x * uu.x + tt.y * uu.y;
                    ci += tt.x * uu.y - tt.y * uu.x;
                }
#pragma unroll
                for (int off = 16; off; off >>= 1) {
                    cr += __shfl_xor_sync(0xffffffffu, cr, off);
                    ci += __shfl_xor_sync(0xffffffffu, ci, off);
                }
#pragma unroll
                for (int rs = 0; rs < 4; ++rs) {
                    int r = lane + 32 * rs;
                    float2 tt = sT[r];
                    v[cs][rs].x -= cr * tt.x - ci * tt.y;
                    v[cs][rs].y -= cr * tt.y + ci * tt.x;
                    float2 gg = sGT[r];
                    float2 uu = sU[j * 130 + r];
                    uu.x -= cr * gg.x - ci * gg.y;
                    uu.y -= cr * gg.y + ci * gg.x;
                    sU[j * 130 + r] = uu;
                }
            }
        }
        __syncthreads();
    }
}

// ---------------- apply: Q = A * W, write (m, r, 2) output layout -------------------
__global__ __launch_bounds__(256)
void apply_kernel(const float2* __restrict__ A0, const float2* __restrict__ A1,
                  const float2* __restrict__ gW, float* __restrict__ out) {
    const int mat = blockIdx.y;
    const float2* A = (mat == 0) ? A0 : A1;
    const float2* W = gW + mat * 128 * 128;
    float2* outp = (float2*)(out + ((mat == 0) ? 0 : (131072 + 128)));
    const int lane = threadIdx.x & 31, warp = threadIdx.x >> 5;
    const int j = blockIdx.x * 8 + warp;

    float2 acc[16];
#pragma unroll
    for (int s = 0; s < 16; ++s) acc[s] = make_float2(0.f, 0.f);

#pragma unroll 1
    for (int k = 0; k <= j; ++k) {                // t_j support: rows 0..j
        float2 w = __ldg(&W[j * 128 + k]);
        const float2* ak = A + (size_t)k * 512;
#pragma unroll
        for (int s = 0; s < 16; ++s) {
            float2 a = ak[lane + 32 * s];
            acc[s].x += w.x * a.x - w.y * a.y;
            acc[s].y += w.x * a.y + w.y * a.x;
        }
    }
#pragma unroll
    for (int s = 0; s < 16; ++s)
        outp[(size_t)(lane + 32 * s) * 128 + j] = acc[s];
}

// ---------------- launch ----------------
extern "C" void kernel_launch(void* const* d_in, const int* in_sizes, int n_in,
                              void* d_out, int out_size) {
    const float* x   = (const float*)d_in[0];
    const float* cw1 = (const float*)d_in[1];  const float* cb1 = (const float*)d_in[2];
    const float* cw2 = (const float*)d_in[3];  const float* cb2 = (const float*)d_in[4];
    const float* cw3 = (const float*)d_in[5];  const float* cb3 = (const float*)d_in[6];
    const float* fw1 = (const float*)d_in[7];  const float* fb1 = (const float*)d_in[8];
    const float* fw2 = (const float*)d_in[9];  const float* fb2 = (const float*)d_in[10];
    const float* sw1 = (const float*)d_in[11]; const float* sb1 = (const float*)d_in[12];
    const float* sw2 = (const float*)d_in[13]; const float* sb2 = (const float*)d_in[14];
    const float* uw1 = (const float*)d_in[15]; const float* ub1 = (const float*)d_in[16];
    const float* uw2 = (const float*)d_in[17]; const float* ub2 = (const float*)d_in[18];
    const float* vw1 = (const float*)d_in[19]; const float* vb1 = (const float*)d_in[20];
    const float* vw2 = (const float*)d_in[21]; const float* vb2 = (const float*)d_in[22];
    float* out = (float*)d_out;

    float *xchw, *h1, *h2p, *h3, *feat, *f2g, *u1, *v1;
    float2 *Ut, *Vt, *G, *W;
    cudaGetSymbolAddress((void**)&xchw, g_xchw);
    cudaGetSymbolAddress((void**)&h1,   g_h1);
    cudaGetSymbolAddress((void**)&h2p,  g_h2p);
    cudaGetSymbolAddress((void**)&h3,   g_h3);
    cudaGetSymbolAddress((void**)&feat, g_feat);
    cudaGetSymbolAddress((void**)&f2g,  g_f2);
    cudaGetSymbolAddress((void**)&u1,   g_u1);
    cudaGetSymbolAddress((void**)&v1,   g_v1);
    cudaGetSymbolAddress((void**)&Ut,   g_Ut);
    cudaGetSymbolAddress((void**)&Vt,   g_Vt);
    cudaGetSymbolAddress((void**)&G,    g_G);
    cudaGetSymbolAddress((void**)&W,    g_W);

    const int c2p_smem = C2P_SMEM_FLOATS * 4;   // 72960 B
    const int cmm_smem = CMM_SMEM_FLOATS * 4;   // 64768 B
    const int gsg_smem = GSG_SMEM_BYTES;        // 135168 B
    cudaFuncSetAttribute(conv2_mma_pool, cudaFuncAttributeMaxDynamicSharedMemorySize, c2p_smem);
    cudaFuncSetAttribute(conv3x3_mma<64>, cudaFuncAttributeMaxDynamicSharedMemorySize, cmm_smem);
    cudaFuncSetAttribute(gsgram_kernel, cudaFuncAttributeMaxDynamicSharedMemorySize, gsg_smem);

    prep_x_kernel<<<1024, 256>>>(x, xchw);
    conv3x3_relu<2><<<dim3(2, 512, 2), 128, 16 * 2 * 9 * 4>>>(xchw, cw1, cb1, h1, 512, 512);
    conv2_mma_pool<<<dim3(4, 256, 1), 256, c2p_smem>>>(h1, cw2, cb2, h2p);
    conv3x3_mma<64><<<dim3(2, 256, 2), 256, cmm_smem>>>(h2p, cw3, cb3, h3, 256, 256);
    avgpool_kernel<<<128, 256>>>(h3, feat);
    small_layers_kernel<<<1, 512>>>(feat, fw1, fb1, fw2, fb2, sw1, sb1, sw2, sb2,
                                    f2g, out + 131072);
    u1v1_kernel<<<128, 256>>>(uw1, ub1, vw1, vb1, f2g, u1, v1);
    big_head_kernel<<<2048, 256>>>(uw2, ub2, vw2, vb2, u1, v1, (float*)Ut, (float*)Vt);

    gram_kernel<<<dim3(128, 2), 256>>>(Ut, Vt, G);
    gsgram_kernel<<<2, 1024, gsg_smem>>>(G, W);
    apply_kernel<<<dim3(16, 2), 256>>>(Ut, Vt, W, out);
}

// round 16
// speedup vs baseline: 1.1685x; 1.1685x over previous
#include <cuda_runtime.h>
#include <cuda_bf16.h>
#include <cstdint>
#include <cstddef>

// ---------------- scratch (static __device__ arrays; no cudaMalloc) ----------------
static __device__ float  g_xchw[2 * 512 * 512];
static __device__ float  g_h1 [32 * 512 * 512];
static __device__ float  g_h2p[64 * 256 * 256];
static __device__ float  g_h3 [128 * 256 * 256];
static __device__ float  g_feat[128];
static __device__ float  g_f2[512];
static __device__ float  g_u1[512];
static __device__ float  g_v1[512];
static __device__ float2 g_Ut[128 * 512];      // column-contiguous: [r][m]
static __device__ float2 g_Vt[128 * 512];
static __device__ float2 g_G [2 * 128 * 128];  // FULL Gram matrices
static __device__ float2 g_W [2 * 128 * 128];  // MGS transform: Q = A * W (cols t_j)

// ---------------- (H,W,2) -> CHW transpose ----------------
__global__ void prep_x_kernel(const float* __restrict__ x, float* __restrict__ xchw) {
    int idx = blockIdx.x * 256 + threadIdx.x;   // 512*512 exactly
    float2 v = reinterpret_cast<const float2*>(x)[idx];
    xchw[idx] = v.x;
    xchw[512 * 512 + idx] = v.y;
}

// ---------------- scalar direct conv (used only for tiny conv1, CIN=2) ------------
template<int CIN>
__global__ __launch_bounds__(128)
void conv3x3_relu(const float* __restrict__ in, const float* __restrict__ wt,
                  const float* __restrict__ bias, float* __restrict__ out,
                  int H, int W) {
    extern __shared__ float sw[];               // 16 * CIN * 9 floats
    const int tid = threadIdx.x;
    const int obase = blockIdx.z * 16;
    for (int idx = tid; idx < 16 * CIN * 9; idx += 128)
        sw[idx] = wt[obase * CIN * 9 + idx];
    __syncthreads();

    const int og = tid >> 6;
    const int pg = tid & 63;
    const int h  = blockIdx.y;
    const int x0 = blockIdx.x * 256 + pg * 4;

    float acc[8][4];
#pragma unroll
    for (int a = 0; a < 8; ++a)
#pragma unroll
        for (int p = 0; p < 4; ++p) acc[a][p] = 0.f;

#pragma unroll
    for (int c = 0; c < CIN; ++c) {
#pragma unroll
        for (int ky = 0; ky < 3; ++ky) {
            const int yy = h + ky - 1;
            const bool yv = ((unsigned)yy < (unsigned)H);
            const float* ip = in + ((size_t)c * H + yy) * W;
            float r[6];
#pragma unroll
            for (int dx = 0; dx < 6; ++dx) {
                int xx = x0 - 1 + dx;
                r[dx] = (yv && (unsigned)xx < (unsigned)W) ? __ldg(ip + xx) : 0.f;
            }
            const float* swp = sw + (og * 8) * (CIN * 9) + c * 9 + ky * 3;
#pragma unroll
            for (int kx = 0; kx < 3; ++kx) {
#pragma unroll
                for (int oo = 0; oo < 8; ++oo) {
                    float wv = swp[oo * (CIN * 9) + kx];
                    acc[oo][0] = fmaf(wv, r[kx + 0], acc[oo][0]);
                    acc[oo][1] = fmaf(wv, r[kx + 1], acc[oo][1]);
                    acc[oo][2] = fmaf(wv, r[kx + 2], acc[oo][2]);
                    acc[oo][3] = fmaf(wv, r[kx + 3], acc[oo][3]);
                }
            }
        }
    }
#pragma unroll
    for (int oo = 0; oo < 8; ++oo) {
        const int o = obase + og * 8 + oo;
        const float b = bias[o];
        float4 res;
        res.x = fmaxf(acc[oo][0] + b, 0.f); res.y = fmaxf(acc[oo][1] + b, 0.f);
        res.z = fmaxf(acc[oo][2] + b, 0.f); res.w = fmaxf(acc[oo][3] + b, 0.f);
        *reinterpret_cast<float4*>(out + ((size_t)o * H + h) * W + x0) = res;
    }
}

// ---------------- bf16 helpers ----------------
__device__ __forceinline__ void mma_bf16(float* c, uint32_t a0, uint32_t a1,
                                         uint32_t a2, uint32_t a3,
                                         uint32_t b0, uint32_t b1) {
    asm volatile(
        "mma.sync.aligned.m16n8k16.row.col.f32.bf16.bf16.f32 "
        "{%0,%1,%2,%3}, {%4,%5,%6,%7}, {%8,%9}, {%0,%1,%2,%3};"
        : "+f"(c[0]), "+f"(c[1]), "+f"(c[2]), "+f"(c[3])
        : "r"(a0), "r"(a1), "r"(a2), "r"(a3), "r"(b0), "r"(b1));
}
// pack 2 floats into (hi_pair, lo_pair): hi/lo bf16 split, low 16 bits = first elem
__device__ __forceinline__ uint2 bfsplit2(float v0, float v1) {
    __nv_bfloat16 h0 = __float2bfloat16_rn(v0);
    __nv_bfloat16 h1 = __float2bfloat16_rn(v1);
    __nv_bfloat16 l0 = __float2bfloat16_rn(v0 - __bfloat162float(h0));
    __nv_bfloat16 l1 = __float2bfloat16_rn(v1 - __bfloat162float(h1));
    __nv_bfloat162 hp = __halves2bfloat162(h0, h1);   // .x low bits
    __nv_bfloat162 lp = __halves2bfloat162(l0, l1);
    uint2 r;
    r.x = *reinterpret_cast<uint32_t*>(&hp);
    r.y = *reinterpret_cast<uint32_t*>(&lp);
    return r;
}

// X smem: 8 channel-pair planes (pair p = channels 2p,2p+1), one uint2 per pixel
// = (hi_pair, lo_pair). Plane stride ≡ 4 (mod 16) uint2 -> LDS.64 conflict-free.
// W smem: uint2 w2[oc][76] at s*8+p, stride 76 ≡ 4 (mod 16) -> conflict-free.

// ---------------- conv2 (32->64) bf16 MMA, fused 2x2 maxpool ----------------
// X planes: 4 rows x 130 px = 520 pixels, plane stride 532 uint2.
// bytes: x2 8*532*8=34048 | w2 64*76*8=38912 = 72960
#define C2P_SMEM_BYTES 72960
#define PX2 532
__global__ __launch_bounds__(256)
void conv2_mma_pool(const float* __restrict__ in, const float* __restrict__ wt,
                    const float* __restrict__ bias, float* __restrict__ out) {
    extern __shared__ uint2 smu[];
    uint2* x2 = smu;                   // 8*532
    uint2* w2 = smu + 8 * PX2;         // 64*76

    const int t = threadIdx.x;
    const int lane = t & 31, warp = t >> 5;
    const int g = lane >> 2, tg = lane & 3;
    const int mwarp = warp & 3, nwarp = warp >> 2;
    const int x0 = blockIdx.x * 128;
    const int y0 = blockIdx.y * 2;

    float acc[2][8][4];
#pragma unroll
    for (int ry = 0; ry < 2; ++ry)
#pragma unroll
        for (int nt = 0; nt < 8; ++nt)
#pragma unroll
            for (int i = 0; i < 4; ++i) acc[ry][nt][i] = 0.f;

#pragma unroll 1
    for (int c0 = 0; c0 < 2; ++c0) {    // 32 in-ch / 16
        __syncthreads();
        // X slab: 8 pairs x 4 rows x 130 px
        for (int idx = t; idx < 4160; idx += 256) {
            int p  = idx / 520;
            int rr = idx - p * 520;                 // r*130 + x
            int r  = rr / 130, x = rr - r * 130;
            int yy = y0 + r - 1, xx = x0 + x - 1;
            float v0 = 0.f, v1 = 0.f;
            if ((unsigned)yy < 512u && (unsigned)xx < 512u) {
                const float* base = in + ((size_t)(c0 * 16 + 2 * p) * 512 + yy) * 512 + xx;
                v0 = __ldg(base);
                v1 = __ldg(base + 512 * 512);
            }
            x2[p * PX2 + rr] = bfsplit2(v0, v1);
        }
        // W slab: 64 oc x 9 shifts x 8 pairs
        for (int idx = t; idx < 4608; idx += 256) {
            int o = idx / 72, r = idx - o * 72;
            int s = r >> 3, p = r & 7;
            const float* wp = wt + ((size_t)o * 32 + c0 * 16 + 2 * p) * 9 + s;
            w2[o * 76 + s * 8 + p] = bfsplit2(__ldg(wp), __ldg(wp + 9));
        }
        __syncthreads();

#pragma unroll
        for (int ky = 0; ky < 3; ++ky) {
#pragma unroll
            for (int kx = 0; kx < 3; ++kx) {
                const int s = ky * 3 + kx;
                const uint2* pw = w2 + (mwarp * 16 + g) * 76 + s * 8 + tg;
                uint2 A0 = pw[0];
                uint2 A2 = pw[4];
                uint2 A1 = pw[8 * 76];
                uint2 A3 = pw[8 * 76 + 4];
#pragma unroll
                for (int ry = 0; ry < 2; ++ry) {
                    const int fb = tg * PX2 + (ky + ry) * 130 + nwarp * 64 + g + kx;
#pragma unroll
                    for (int nt = 0; nt < 8; ++nt) {
                        uint2 B0 = x2[fb + nt * 8];
                        uint2 B1 = x2[fb + 4 * PX2 + nt * 8];
                        mma_bf16(acc[ry][nt], A0.x, A1.x, A2.x, A3.x, B0.x, B1.x);
                        mma_bf16(acc[ry][nt], A0.y, A1.y, A2.y, A3.y, B0.x, B1.x);
                        mma_bf16(acc[ry][nt], A0.x, A1.x, A2.x, A3.x, B0.y, B1.y);
                    }
                }
            }
        }
    }

    const int o_lo = mwarp * 16 + g;
    const float b_lo = __ldg(bias + o_lo);
    const float b_hi = __ldg(bias + o_lo + 8);
    float* rowp_lo = out + ((size_t)o_lo * 256 + blockIdx.y) * 256;
    float* rowp_hi = out + ((size_t)(o_lo + 8) * 256 + blockIdx.y) * 256;
#pragma unroll
    for (int nt = 0; nt < 8; ++nt) {
        int xp = x0 / 2 + nwarp * 32 + nt * 4 + tg;
        float l00 = fmaxf(acc[0][nt][0] + b_lo, 0.f), l01 = fmaxf(acc[0][nt][1] + b_lo, 0.f);
        float l10 = fmaxf(acc[1][nt][0] + b_lo, 0.f), l11 = fmaxf(acc[1][nt][1] + b_lo, 0.f);
        rowp_lo[xp] = fmaxf(fmaxf(l00, l01), fmaxf(l10, l11));
        float h00 = fmaxf(acc[0][nt][2] + b_hi, 0.f), h01 = fmaxf(acc[0][nt][3] + b_hi, 0.f);
        float h10 = fmaxf(acc[1][nt][2] + b_hi, 0.f), h11 = fmaxf(acc[1][nt][3] + b_hi, 0.f);
        rowp_hi[xp] = fmaxf(fmaxf(h00, h01), fmaxf(h10, h11));
    }
}

// ---------------- conv3 bf16 MMA ----------------
// X planes: 3 rows x 130 = 390 pixels, plane stride 404 uint2.
// bytes: x2 8*404*8=25856 | w2 38912 = 64768
#define CMM_SMEM_BYTES 64768
#define PX3 404
template<int CIN>
__global__ __launch_bounds__(256)
void conv3x3_mma(const float* __restrict__ in, const float* __restrict__ wt,
                 const float* __restrict__ bias, float* __restrict__ out,
                 int H, int W) {
    extern __shared__ uint2 smu[];
    uint2* x2 = smu;                   // 8*404
    uint2* w2 = smu + 8 * PX3;         // 64*76

    const int t = threadIdx.x;
    const int lane = t & 31, warp = t >> 5;
    const int g = lane >> 2, tg = lane & 3;
    const int mwarp = warp & 3, nwarp = warp >> 2;
    const int x0 = blockIdx.x * 128;
    const int y  = blockIdx.y;
    const int obase = blockIdx.z * 64;

    float acc[8][4];
#pragma unroll
    for (int nt = 0; nt < 8; ++nt)
#pragma unroll
        for (int i = 0; i < 4; ++i) acc[nt][i] = 0.f;

#pragma unroll 1
    for (int c0 = 0; c0 < CIN / 16; ++c0) {
        __syncthreads();
        for (int idx = t; idx < 3120; idx += 256) {
            int p  = idx / 390;
            int rr = idx - p * 390;                 // r*130 + x
            int r  = rr / 130, x = rr - r * 130;
            int yy = y + r - 1, xx = x0 + x - 1;
            float v0 = 0.f, v1 = 0.f;
            if ((unsigned)yy < (unsigned)H && (unsigned)xx < (unsigned)W) {
                const float* base = in + ((size_t)(c0 * 16 + 2 * p) * H + yy) * W + xx;
                v0 = __ldg(base);
                v1 = __ldg(base + (size_t)H * W);
            }
            x2[p * PX3 + rr] = bfsplit2(v0, v1);
        }
        for (int idx = t; idx < 4608; idx += 256) {
            int o = idx / 72, r = idx - o * 72;
            int s = r >> 3, p = r & 7;
            const float* wp = wt + ((size_t)(obase + o) * CIN + c0 * 16 + 2 * p) * 9 + s;
            w2[o * 76 + s * 8 + p] = bfsplit2(__ldg(wp), __ldg(wp + 9));
        }
        __syncthreads();

#pragma unroll
        for (int ky = 0; ky < 3; ++ky) {
#pragma unroll
            for (int kx = 0; kx < 3; ++kx) {
                const int s = ky * 3 + kx;
                const uint2* pw = w2 + (mwarp * 16 + g) * 76 + s * 8 + tg;
                uint2 A0 = pw[0];
                uint2 A2 = pw[4];
                uint2 A1 = pw[8 * 76];
                uint2 A3 = pw[8 * 76 + 4];
                const int fb = tg * PX3 + ky * 130 + nwarp * 64 + g + kx;
#pragma unroll
                for (int nt = 0; nt < 8; ++nt) {
                    uint2 B0 = x2[fb + nt * 8];
                    uint2 B1 = x2[fb + 4 * PX3 + nt * 8];
                    mma_bf16(acc[nt], A0.x, A1.x, A2.x, A3.x, B0.x, B1.x);
                    mma_bf16(acc[nt], A0.y, A1.y, A2.y, A3.y, B0.x, B1.x);
                    mma_bf16(acc[nt], A0.x, A1.x, A2.x, A3.x, B0.y, B1.y);
                }
            }
        }
    }

    const int o_lo = obase + mwarp * 16 + g;
    const float b_lo = __ldg(bias + o_lo);
    const float b_hi = __ldg(bias + o_lo + 8);
    float* row_lo = out + ((size_t)o_lo * H + y) * W;
    float* row_hi = out + ((size_t)(o_lo + 8) * H + y) * W;
#pragma unroll
    for (int nt = 0; nt < 8; ++nt) {
        int x = x0 + nwarp * 64 + nt * 8 + 2 * tg;
        float2 v0 = make_float2(fmaxf(acc[nt][0] + b_lo, 0.f),
                                fmaxf(acc[nt][1] + b_lo, 0.f));
        float2 v1 = make_float2(fmaxf(acc[nt][2] + b_hi, 0.f),
                                fmaxf(acc[nt][3] + b_hi, 0.f));
        *reinterpret_cast<float2*>(row_lo + x) = v0;
        *reinterpret_cast<float2*>(row_hi + x) = v1;
    }
}

// ---------------- global average pool: 128 channels of 256x256 ----------------
__global__ void avgpool_kernel(const float* __restrict__ in, float* __restrict__ feat) {
    const int c = blockIdx.x;
    const float* p = in + (size_t)c * 65536;
    float s = 0.f;
    for (int i = threadIdx.x; i < 65536; i += 256) s += p[i];
    __shared__ float sh[256];
    sh[threadIdx.x] = s;
    __syncthreads();
    for (int off = 128; off > 0; off >>= 1) {
        if (threadIdx.x < off) sh[threadIdx.x] += sh[threadIdx.x + off];
        __syncthreads();
    }
    if (threadIdx.x == 0) feat[c] = sh[0] * (1.f / 65536.f);
}

// ---------------- fused small FC trunk + s head (softplus+sort); exports f2 ----------
__device__ __forceinline__ float dot4(const float* __restrict__ w,
                                      const float* __restrict__ v, int n4) {
    float a = 0.f;
    const float4* w4 = (const float4*)w;
    const float4* v4 = (const float4*)v;
#pragma unroll 8
    for (int k = 0; k < n4; ++k) {
        float4 ww = w4[k], vv = v4[k];
        a += ww.x * vv.x + ww.y * vv.y + ww.z * vv.z + ww.w * vv.w;
    }
    return a;
}

__global__ __launch_bounds__(512)
void small_layers_kernel(const float* __restrict__ feat,
    const float* __restrict__ fw1, const float* __restrict__ fb1,
    const float* __restrict__ fw2, const float* __restrict__ fb2,
    const float* __restrict__ sw1, const float* __restrict__ sb1,
    const float* __restrict__ sw2, const float* __restrict__ sb2,
    float* __restrict__ f2g, float* __restrict__ s_out) {
    __shared__ __align__(16) float sf[128];
    __shared__ __align__(16) float f1[256];
    __shared__ __align__(16) float f2[512];
    __shared__ __align__(16) float s1[256];
    __shared__ float sv[128];
    const int t = threadIdx.x;

    if (t < 128) sf[t] = feat[t];
    __syncthreads();

    if (t < 256) f1[t] = fmaxf(fb1[t] + dot4(fw1 + t * 128, sf, 32), 0.f);
    __syncthreads();

    {
        float val = fmaxf(fb2[t] + dot4(fw2 + t * 256, f1, 64), 0.f);
        f2[t] = val;
        f2g[t] = val;
    }
    __syncthreads();

    if (t < 256) s1[t] = fmaxf(sb1[t] + dot4(sw1 + (size_t)t * 512, f2, 128), 0.f);
    __syncthreads();

    if (t < 128) {
        float xv = sb2[t] + dot4(sw2 + t * 256, s1, 64);
        sv[t] = (xv > 0.f) ? (xv + log1pf(expf(-xv))) : log1pf(expf(xv));
    }
    __syncthreads();

    if (t < 128) {
        float v = sv[t];
        int rank = 0;
        for (int j = 0; j < 128; ++j) {
            float o = sv[j];
            rank += (o > v) || (o == v && j > t);
        }
        s_out[rank] = v;
    }
}

// ---------------- u1/v1 matvecs in parallel (1024 warps) ----------------
__global__ __launch_bounds__(256)
void u1v1_kernel(const float* __restrict__ uw1, const float* __restrict__ ub1,
                 const float* __restrict__ vw1, const float* __restrict__ vb1,
                 const float* __restrict__ f2g,
                 float* __restrict__ u1, float* __restrict__ v1) {
    __shared__ __align__(16) float sf[512];
    const int t = threadIdx.x;
    sf[t] = f2g[t]; sf[t + 256] = f2g[t + 256];
    __syncthreads();
    const int lane = t & 31, warp = t >> 5;
    const int row = blockIdx.x * 8 + warp;          // 0..1023
    const float* wrow;
    float b; float* dst;
    if (row < 512) { wrow = uw1 + (size_t)row * 512; b = ub1[row]; dst = u1 + row; }
    else { wrow = vw1 + (size_t)(row - 512) * 512; b = vb1[row - 512]; dst = v1 + (row - 512); }
    float a = 0.f;
    const float4* w4 = (const float4*)wrow;
    const float4* x4 = (const float4*)sf;
#pragma unroll
    for (int k = lane; k < 128; k += 32) {
        float4 ww = w4[k], vv = x4[k];
        a += ww.x * vv.x + ww.y * vv.y + ww.z * vv.z + ww.w * vv.w;
    }
#pragma unroll
    for (int off = 16; off; off >>= 1) a += __shfl_down_sync(0xffffffffu, a, off);
    if (lane == 0) *dst = fmaxf(a + b, 0.f);
}

// ---------------- big head matvecs: 2 x (131072 x 512), write transposed ----------------
__global__ __launch_bounds__(256)
void big_head_kernel(const float* __restrict__ uw2, const float* __restrict__ ub2,
                     const float* __restrict__ vw2, const float* __restrict__ vb2,
                     const float* __restrict__ u1, const float* __restrict__ v1,
                     float* __restrict__ Ut, float* __restrict__ Vt) {
    __shared__ __align__(16) float su[512];
    __shared__ __align__(16) float svv[512];
    const int t = threadIdx.x;
    for (int i = t; i < 512; i += 256) { su[i] = u1[i]; svv[i] = v1[i]; }
    __syncthreads();

    const int lane = t & 31, warp = t >> 5;
    const int gw = blockIdx.x * 8 + warp;
#pragma unroll 1
    for (int rr = 0; rr < 16; ++rr) {
        int e = gw * 16 + rr;
        const float* wrow; const float* xv; float b; float* dst;
        if (e < 131072) {
            wrow = uw2 + (size_t)e * 512; xv = su; b = ub2[e];
            int m = e >> 8, r = (e >> 1) & 127, cp = e & 1;
            dst = Ut + (size_t)(r * 512 + m) * 2 + cp;
        } else {
            int e2 = e - 131072;
            wrow = vw2 + (size_t)e2 * 512; xv = svv; b = vb2[e2];
            int m = e2 >> 8, r = (e2 >> 1) & 127, cp = e2 & 1;
            dst = Vt + (size_t)(r * 512 + m) * 2 + cp;
        }
        float a = 0.f;
        const float4* w4 = (const float4*)wrow;
        const float4* x4 = (const float4*)xv;
#pragma unroll
        for (int k = lane; k < 128; k += 32) {
            float4 ww = w4[k], vv = x4[k];
            a += ww.x * vv.x + ww.y * vv.y + ww.z * vv.z + ww.w * vv.w;
        }
#pragma unroll
        for (int off = 16; off; off >>= 1) a += __shfl_down_sync(0xffffffffu, a, off);
        if (lane == 0) *dst = a + b;
    }
}

// ---------------- Gram: G = A^H A (FULL matrix) ------------------------------------
__global__ __launch_bounds__(256)
void gram_kernel(const float2* __restrict__ A0, const float2* __restrict__ A1,
                 float2* __restrict__ G) {
    const float2* A = (blockIdx.y == 0) ? A0 : A1;
    float2* Gm = G + blockIdx.y * 128 * 128;
    const int p = blockIdx.x;
    const int lane = threadIdx.x & 31, warp = threadIdx.x >> 5;
    const float2* ap = A + (size_t)p * 512;
    for (int q = warp; q < 128; q += 8) {
        const float2* aq = A + (size_t)q * 512;
        float cr = 0.f, ci = 0.f;
#pragma unroll
        for (int k = 0; k < 16; ++k) {
            float2 xp = ap[lane + 32 * k], xq = aq[lane + 32 * k];
            cr += xp.x * xq.x + xp.y * xq.y;    // re(conj(a_p) . a_q)
            ci += xp.x * xq.y - xp.y * xq.x;    // im
        }
#pragma unroll
        for (int off = 16; off; off >>= 1) {
            cr += __shfl_xor_sync(0xffffffffu, cr, off);
            ci += __shfl_xor_sync(0xffffffffu, ci, off);
        }
        if (lane == 0) Gm[p * 128 + q] = make_float2(cr, ci);
    }
}

// ---------------- Gram-space MGS with eps (EXACT reference semantics) --------------
#define GSG_SMEM_BYTES (128 * 130 * 8 + 2 * 128 * 8)
__global__ __launch_bounds__(1024, 1)
void gsgram_kernel(const float2* __restrict__ G, float2* __restrict__ gW) {
    extern __shared__ float2 sm2[];
    float2* sU  = sm2;                 // [col][row], col stride 130
    float2* sT  = sm2 + 128 * 130;     // t_i broadcast
    float2* sGT = sT + 128;            // (G t_i) broadcast
    const float2* Gm = G + blockIdx.x * 128 * 128;
    float2* Wm = gW + blockIdx.x * 128 * 128;
    const int t = threadIdx.x, lane = t & 31, warp = t >> 5;

    for (int idx = t; idx < 16384; idx += 1024) {
        int r = idx >> 7, j = idx & 127;
        sU[j * 130 + r] = Gm[r * 128 + j];
    }

    float2 v[4][4];                                // [colslot][rowslot]
#pragma unroll
    for (int cs = 0; cs < 4; ++cs)
#pragma unroll
        for (int rs = 0; rs < 4; ++rs) v[cs][rs] = make_float2(0.f, 0.f);
    if (lane == warp) {
#pragma unroll
        for (int cs = 0; cs < 4; ++cs) v[cs][cs] = make_float2(1.f, 0.f);
    }
    __syncthreads();

#pragma unroll 1
    for (int i = 0; i < 128; ++i) {
        const int iw = i & 31, is = i >> 5;
        if (warp == iw) {
            float d2 = 0.f;
#pragma unroll
            for (int rs = 0; rs < 4; ++rs) {
                float2 vv = v[is][rs];
                float2 uu = sU[i * 130 + lane + 32 * rs];
                d2 += vv.x * uu.x + vv.y * uu.y;
            }
#pragma unroll
            for (int off = 16; off; off >>= 1) d2 += __shfl_xor_sync(0xffffffffu, d2, off);
            const float inv = 1.f / sqrtf(d2 + 1e-8f);   // reference epsilon, exactly
#pragma unroll
            for (int rs = 0; rs < 4; ++rs) {
                int r = lane + 32 * rs;
                float2 vv = v[is][rs];
                float2 tv = make_float2(vv.x * inv, vv.y * inv);
                sT[r] = tv;
                Wm[i * 128 + r] = tv;
                float2 uu = sU[i * 130 + r];
                sGT[r] = make_float2(uu.x * inv, uu.y * inv);
            }
        }
        __syncthreads();
#pragma unroll
        for (int cs = 0; cs < 4; ++cs) {
            const int j = warp + 32 * cs;
            if (j > i) {
                float cr = 0.f, ci = 0.f;
#pragma unroll
                for (int rs = 0; rs < 4; ++rs) {
                    int r = lane + 32 * rs;
                    float2 tt = sT[r];
                    float2 uu = sU[j * 130 + r];
                    cr += tt.x * uu.x + tt.y * uu.y;
                    ci += tt.x * uu.y - tt.y * uu.x;
                }
#pragma unroll
                for (int off = 16; off; off >>= 1) {
                    cr += __shfl_xor_sync(0xffffffffu, cr, off);
                    ci += __shfl_xor_sync(0xffffffffu, ci, off);
                }
#pragma unroll
                for (int rs = 0; rs < 4; ++rs) {
                    int r = lane + 32 * rs;
                    float2 tt = sT[r];
                    v[cs][rs].x -= cr * tt.x - ci * tt.y;
                    v[cs][rs].y -= cr * tt.y + ci * tt.x;
                    float2 gg = sGT[r];
                    float2 uu = sU[j * 130 + r];
                    uu.x -= cr * gg.x - ci * gg.y;
                    uu.y -= cr * gg.y + ci * gg.x;
                    sU[j * 130 + r] = uu;
                }
            }
        }
        __syncthreads();
    }
}

// ---------------- apply: Q = A * W, write (m, r, 2) output layout -------------------
__global__ __launch_bounds__(256)
void apply_kernel(const float2* __restrict__ A0, const float2* __restrict__ A1,
                  const float2* __restrict__ gW, float* __restrict__ out) {
    const int mat = blockIdx.y;
    const float2* A = (mat == 0) ? A0 : A1;
    const float2* W = gW + mat * 128 * 128;
    float2* outp = (float2*)(out + ((mat == 0) ? 0 : (131072 + 128)));
    const int lane = threadIdx.x & 31, warp = threadIdx.x >> 5;
    const int j = blockIdx.x * 8 + warp;

    float2 acc[16];
#pragma unroll
    for (int s = 0; s < 16; ++s) acc[s] = make_float2(0.f, 0.f);

#pragma unroll 1
    for (int k = 0; k <= j; ++k) {                // t_j support: rows 0..j
        float2 w = __ldg(&W[j * 128 + k]);
        const float2* ak = A + (size_t)k * 512;
#pragma unroll
        for (int s = 0; s < 16; ++s) {
            float2 a = ak[lane + 32 * s];
            acc[s].x += w.x * a.x - w.y * a.y;
            acc[s].y += w.x * a.y + w.y * a.x;
        }
    }
#pragma unroll
    for (int s = 0; s < 16; ++s)
        outp[(size_t)(lane + 32 * s) * 128 + j] = acc[s];
}

// ---------------- launch ----------------
extern "C" void kernel_launch(void* const* d_in, const int* in_sizes, int n_in,
                              void* d_out, int out_size) {
    const float* x   = (const float*)d_in[0];
    const float* cw1 = (const float*)d_in[1];  const float* cb1 = (const float*)d_in[2];
    const float* cw2 = (const float*)d_in[3];  const float* cb2 = (const float*)d_in[4];
    const float* cw3 = (const float*)d_in[5];  const float* cb3 = (const float*)d_in[6];
    const float* fw1 = (const float*)d_in[7];  const float* fb1 = (const float*)d_in[8];
    const float* fw2 = (const float*)d_in[9];  const float* fb2 = (const float*)d_in[10];
    const float* sw1 = (const float*)d_in[11]; const float* sb1 = (const float*)d_in[12];
    const float* sw2 = (const float*)d_in[13]; const float* sb2 = (const float*)d_in[14];
    const float* uw1 = (const float*)d_in[15]; const float* ub1 = (const float*)d_in[16];
    const float* uw2 = (const float*)d_in[17]; const float* ub2 = (const float*)d_in[18];
    const float* vw1 = (const float*)d_in[19]; const float* vb1 = (const float*)d_in[20];
    const float* vw2 = (const float*)d_in[21]; const float* vb2 = (const float*)d_in[22];
    float* out = (float*)d_out;

    float *xchw, *h1, *h2p, *h3, *feat, *f2g, *u1, *v1;
    float2 *Ut, *Vt, *G, *W;
    cudaGetSymbolAddress((void**)&xchw, g_xchw);
    cudaGetSymbolAddress((void**)&h1,   g_h1);
    cudaGetSymbolAddress((void**)&h2p,  g_h2p);
    cudaGetSymbolAddress((void**)&h3,   g_h3);
    cudaGetSymbolAddress((void**)&feat, g_feat);
    cudaGetSymbolAddress((void**)&f2g,  g_f2);
    cudaGetSymbolAddress((void**)&u1,   g_u1);
    cudaGetSymbolAddress((void**)&v1,   g_v1);
    cudaGetSymbolAddress((void**)&Ut,   g_Ut);
    cudaGetSymbolAddress((void**)&Vt,   g_Vt);
    cudaGetSymbolAddress((void**)&G,    g_G);
    cudaGetSymbolAddress((void**)&W,    g_W);

    const int gsg_smem = GSG_SMEM_BYTES;        // 135168 B
    cudaFuncSetAttribute(conv2_mma_pool, cudaFuncAttributeMaxDynamicSharedMemorySize,
                         C2P_SMEM_BYTES);
    cudaFuncSetAttribute(conv3x3_mma<64>, cudaFuncAttributeMaxDynamicSharedMemorySize,
                         CMM_SMEM_BYTES);
    cudaFuncSetAttribute(gsgram_kernel, cudaFuncAttributeMaxDynamicSharedMemorySize, gsg_smem);

    prep_x_kernel<<<1024, 256>>>(x, xchw);
    conv3x3_relu<2><<<dim3(2, 512, 2), 128, 16 * 2 * 9 * 4>>>(xchw, cw1, cb1, h1, 512, 512);
    conv2_mma_pool<<<dim3(4, 256, 1), 256, C2P_SMEM_BYTES>>>(h1, cw2, cb2, h2p);
    conv3x3_mma<64><<<dim3(2, 256, 2), 256, CMM_SMEM_BYTES>>>(h2p, cw3, cb3, h3, 256, 256);
    avgpool_kernel<<<128, 256>>>(h3, feat);
    small_layers_kernel<<<1, 512>>>(feat, fw1, fb1, fw2, fb2, sw1, sb1, sw2, sb2,
                                    f2g, out + 131072);
    u1v1_kernel<<<128, 256>>>(uw1, ub1, vw1, vb1, f2g, u1, v1);
    big_head_kernel<<<2048, 256>>>(uw2, ub2, vw2, vb2, u1, v1, (float*)Ut, (float*)Vt);

    gram_kernel<<<dim3(128, 2), 256>>>(Ut, Vt, G);
    gsgram_kernel<<<2, 1024, gsg_smem>>>(G, W);
    apply_kernel<<<dim3(16, 2), 256>>>(Ut, Vt, W, out);
}

// round 17
// speedup vs baseline: 1.1871x; 1.0160x over previous
#include <cuda_runtime.h>
#include <cuda_bf16.h>
#include <cstdint>
#include <cstddef>

// ---------------- scratch (static __device__ arrays; no cudaMalloc) ----------------
static __device__ float  g_xchw[2 * 512 * 512];
static __device__ uint2  g_h1p [16 * 512 * 512];   // conv1 out, bf16-split pairs (2q,2q+1)
static __device__ uint2  g_h2pb[32 * 256 * 256];   // pooled conv2 out, pairs (c, c+8) per 16-chunk
static __device__ float  g_h3 [128 * 256 * 256];
static __device__ float  g_feat[128];
static __device__ float  g_f2[512];
static __device__ float  g_u1[512];
static __device__ float  g_v1[512];
static __device__ float2 g_Ut[128 * 512];      // column-contiguous: [r][m]
static __device__ float2 g_Vt[128 * 512];
static __device__ float2 g_G [2 * 128 * 128];  // FULL Gram matrices
static __device__ float2 g_W [2 * 128 * 128];  // MGS transform: Q = A * W (cols t_j)

// ---------------- bf16 helpers ----------------
__device__ __forceinline__ void mma_bf16(float* c, uint32_t a0, uint32_t a1,
                                         uint32_t a2, uint32_t a3,
                                         uint32_t b0, uint32_t b1) {
    asm volatile(
        "mma.sync.aligned.m16n8k16.row.col.f32.bf16.bf16.f32 "
        "{%0,%1,%2,%3}, {%4,%5,%6,%7}, {%8,%9}, {%0,%1,%2,%3};"
        : "+f"(c[0]), "+f"(c[1]), "+f"(c[2]), "+f"(c[3])
        : "r"(a0), "r"(a1), "r"(a2), "r"(a3), "r"(b0), "r"(b1));
}
// pack 2 floats into (hi_pair, lo_pair): hi/lo bf16 split, low 16 bits = first elem
__device__ __forceinline__ uint2 bfsplit2(float v0, float v1) {
    __nv_bfloat16 h0 = __float2bfloat16_rn(v0);
    __nv_bfloat16 h1 = __float2bfloat16_rn(v1);
    __nv_bfloat16 l0 = __float2bfloat16_rn(v0 - __bfloat162float(h0));
    __nv_bfloat16 l1 = __float2bfloat16_rn(v1 - __bfloat162float(h1));
    __nv_bfloat162 hp = __halves2bfloat162(h0, h1);   // .x low bits
    __nv_bfloat162 lp = __halves2bfloat162(l0, l1);
    uint2 r;
    r.x = *reinterpret_cast<uint32_t*>(&hp);
    r.y = *reinterpret_cast<uint32_t*>(&lp);
    return r;
}

// ---------------- (H,W,2) -> CHW transpose ----------------
__global__ void prep_x_kernel(const float* __restrict__ x, float* __restrict__ xchw) {
    int idx = blockIdx.x * 256 + threadIdx.x;   // 512*512 exactly
    float2 v = reinterpret_cast<const float2*>(x)[idx];
    xchw[idx] = v.x;
    xchw[512 * 512 + idx] = v.y;
}

// ---------------- conv1 scalar (CIN=2), emits bf16-split pair planes ---------------
template<int CIN>
__global__ __launch_bounds__(128)
void conv3x3_relu(const float* __restrict__ in, const float* __restrict__ wt,
                  const float* __restrict__ bias, uint2* __restrict__ outp,
                  int H, int W) {
    extern __shared__ float sw[];               // 16 * CIN * 9 floats
    const int tid = threadIdx.x;
    const int obase = blockIdx.z * 16;
    for (int idx = tid; idx < 16 * CIN * 9; idx += 128)
        sw[idx] = wt[obase * CIN * 9 + idx];
    __syncthreads();

    const int og = tid >> 6;
    const int pg = tid & 63;
    const int h  = blockIdx.y;
    const int x0 = blockIdx.x * 256 + pg * 4;

    float acc[8][4];
#pragma unroll
    for (int a = 0; a < 8; ++a)
#pragma unroll
        for (int p = 0; p < 4; ++p) acc[a][p] = 0.f;

#pragma unroll
    for (int c = 0; c < CIN; ++c) {
#pragma unroll
        for (int ky = 0; ky < 3; ++ky) {
            const int yy = h + ky - 1;
            const bool yv = ((unsigned)yy < (unsigned)H);
            const float* ip = in + ((size_t)c * H + yy) * W;
            float r[6];
#pragma unroll
            for (int dx = 0; dx < 6; ++dx) {
                int xx = x0 - 1 + dx;
                r[dx] = (yv && (unsigned)xx < (unsigned)W) ? __ldg(ip + xx) : 0.f;
            }
            const float* swp = sw + (og * 8) * (CIN * 9) + c * 9 + ky * 3;
#pragma unroll
            for (int kx = 0; kx < 3; ++kx) {
#pragma unroll
                for (int oo = 0; oo < 8; ++oo) {
                    float wv = swp[oo * (CIN * 9) + kx];
                    acc[oo][0] = fmaf(wv, r[kx + 0], acc[oo][0]);
                    acc[oo][1] = fmaf(wv, r[kx + 1], acc[oo][1]);
                    acc[oo][2] = fmaf(wv, r[kx + 2], acc[oo][2]);
                    acc[oo][3] = fmaf(wv, r[kx + 3], acc[oo][3]);
                }
            }
        }
    }
    // emit pairs (even, odd) as bf16-split uint2 planes
#pragma unroll
    for (int j = 0; j < 4; ++j) {
        const int ch = obase + og * 8 + 2 * j;
        const float b0 = bias[ch], b1 = bias[ch + 1];
        uint2* dst = outp + ((size_t)(ch >> 1) * H + h) * W + x0;
#pragma unroll
        for (int p = 0; p < 4; ++p) {
            float v0 = fmaxf(acc[2 * j][p] + b0, 0.f);
            float v1 = fmaxf(acc[2 * j + 1][p] + b1, 0.f);
            dst[p] = bfsplit2(v0, v1);
        }
    }
}

// X smem: 8 pair planes of uint2 = (hi_pair, lo_pair). Plane stride ≡ 4 (mod 16)
// uint2 -> LDS.64 conflict-free. W smem: uint2 w2[oc][76], stride 76 ≡ 4 (mod 16).

// ---------------- conv2 (32->64) bf16 MMA + fused 2x2 maxpool ----------------------
// input: g_h1p pair planes (2q,2q+1). output: g_h2pb pair planes (c, c+8).
// X planes: 4 rows x 130 px = 520 px, plane stride 532 uint2.
#define C2P_SMEM_BYTES 72960
#define PX2 532
__global__ __launch_bounds__(256)
void conv2_mma_pool(const uint2* __restrict__ in, const float* __restrict__ wt,
                    const float* __restrict__ bias, uint2* __restrict__ outp) {
    extern __shared__ uint2 smu[];
    uint2* x2 = smu;                   // 8*532
    uint2* w2 = smu + 8 * PX2;         // 64*76

    const int t = threadIdx.x;
    const int lane = t & 31, warp = t >> 5;
    const int g = lane >> 2, tg = lane & 3;
    const int mwarp = warp & 3, nwarp = warp >> 2;
    const int x0 = blockIdx.x * 128;
    const int y0 = blockIdx.y * 2;

    float acc[2][8][4];
#pragma unroll
    for (int ry = 0; ry < 2; ++ry)
#pragma unroll
        for (int nt = 0; nt < 8; ++nt)
#pragma unroll
            for (int i = 0; i < 4; ++i) acc[ry][nt][i] = 0.f;

#pragma unroll 1
    for (int c0 = 0; c0 < 2; ++c0) {    // 32 in-ch / 16
        __syncthreads();
        // X slab: straight LDG.64 copy (pairs already split in global)
        for (int idx = t; idx < 4160; idx += 256) {
            int p  = idx / 520;
            int rr = idx - p * 520;                 // r*130 + x
            int r  = rr / 130, x = rr - r * 130;
            int yy = y0 + r - 1, xx = x0 + x - 1;
            uint2 v = make_uint2(0u, 0u);
            if ((unsigned)yy < 512u && (unsigned)xx < 512u)
                v = __ldg(&in[((size_t)(c0 * 8 + p) * 512 + yy) * 512 + xx]);
            x2[p * PX2 + rr] = v;
        }
        // W slab: 64 oc x 9 shifts x 8 pairs (channels 2p,2p+1)
        for (int idx = t; idx < 4608; idx += 256) {
            int o = idx / 72, r = idx - o * 72;
            int s = r >> 3, p = r & 7;
            const float* wp = wt + ((size_t)o * 32 + c0 * 16 + 2 * p) * 9 + s;
            w2[o * 76 + s * 8 + p] = bfsplit2(__ldg(wp), __ldg(wp + 9));
        }
        __syncthreads();

#pragma unroll
        for (int ky = 0; ky < 3; ++ky) {
#pragma unroll
            for (int kx = 0; kx < 3; ++kx) {
                const int s = ky * 3 + kx;
                const uint2* pw = w2 + (mwarp * 16 + g) * 76 + s * 8 + tg;
                uint2 A0 = pw[0];
                uint2 A2 = pw[4];
                uint2 A1 = pw[8 * 76];
                uint2 A3 = pw[8 * 76 + 4];
#pragma unroll
                for (int ry = 0; ry < 2; ++ry) {
                    const int fb = tg * PX2 + (ky + ry) * 130 + nwarp * 64 + g + kx;
#pragma unroll
                    for (int nt = 0; nt < 8; ++nt) {
                        uint2 B0 = x2[fb + nt * 8];
                        uint2 B1 = x2[fb + 4 * PX2 + nt * 8];
                        mma_bf16(acc[ry][nt], A0.x, A1.x, A2.x, A3.x, B0.x, B1.x);
                        mma_bf16(acc[ry][nt], A0.y, A1.y, A2.y, A3.y, B0.x, B1.x);
                        mma_bf16(acc[ry][nt], A0.x, A1.x, A2.x, A3.x, B0.y, B1.y);
                    }
                }
            }
        }
    }

    // epilogue: bias + relu + pool; emit bf16-split pair (o_lo, o_lo+8)
    const int o_lo = mwarp * 16 + g;
    const float b_lo = __ldg(bias + o_lo);
    const float b_hi = __ldg(bias + o_lo + 8);
    uint2* rowp = outp + ((size_t)(mwarp * 8 + g) * 256 + blockIdx.y) * 256;
#pragma unroll
    for (int nt = 0; nt < 8; ++nt) {
        int xp = x0 / 2 + nwarp * 32 + nt * 4 + tg;
        float l00 = fmaxf(acc[0][nt][0] + b_lo, 0.f), l01 = fmaxf(acc[0][nt][1] + b_lo, 0.f);
        float l10 = fmaxf(acc[1][nt][0] + b_lo, 0.f), l11 = fmaxf(acc[1][nt][1] + b_lo, 0.f);
        float pl = fmaxf(fmaxf(l00, l01), fmaxf(l10, l11));
        float h00 = fmaxf(acc[0][nt][2] + b_hi, 0.f), h01 = fmaxf(acc[0][nt][3] + b_hi, 0.f);
        float h10 = fmaxf(acc[1][nt][2] + b_hi, 0.f), h11 = fmaxf(acc[1][nt][3] + b_hi, 0.f);
        float ph = fmaxf(fmaxf(h00, h01), fmaxf(h10, h11));
        rowp[xp] = bfsplit2(pl, ph);
    }
}

// ---------------- conv3 (64->128) bf16 MMA -----------------------------------------
// input: g_h2pb pair planes (c, c+8) per 16-chunk; plane index c0*8+p.
// X planes: 3 rows x 130 = 390 px, plane stride 404 uint2.
#define CMM_SMEM_BYTES 64768
#define PX3 404
template<int CIN>
__global__ __launch_bounds__(256)
void conv3x3_mma(const uint2* __restrict__ in, const float* __restrict__ wt,
                 const float* __restrict__ bias, float* __restrict__ out,
                 int H, int W) {
    extern __shared__ uint2 smu[];
    uint2* x2 = smu;                   // 8*404
    uint2* w2 = smu + 8 * PX3;         // 64*76

    const int t = threadIdx.x;
    const int lane = t & 31, warp = t >> 5;
    const int g = lane >> 2, tg = lane & 3;
    const int mwarp = warp & 3, nwarp = warp >> 2;
    const int x0 = blockIdx.x * 128;
    const int y  = blockIdx.y;
    const int obase = blockIdx.z * 64;

    float acc[8][4];
#pragma unroll
    for (int nt = 0; nt < 8; ++nt)
#pragma unroll
        for (int i = 0; i < 4; ++i) acc[nt][i] = 0.f;

#pragma unroll 1
    for (int c0 = 0; c0 < CIN / 16; ++c0) {
        __syncthreads();
        // X slab: straight LDG.64 copy
        for (int idx = t; idx < 3120; idx += 256) {
            int p  = idx / 390;
            int rr = idx - p * 390;                 // r*130 + x
            int r  = rr / 130, x = rr - r * 130;
            int yy = y + r - 1, xx = x0 + x - 1;
            uint2 v = make_uint2(0u, 0u);
            if ((unsigned)yy < (unsigned)H && (unsigned)xx < (unsigned)W)
                v = __ldg(&in[((size_t)(c0 * 8 + p) * H + yy) * W + xx]);
            x2[p * PX3 + rr] = v;
        }
        // W slab: pairs (c, c+8): offsets p and p+8 within the 16-chunk (+72 floats)
        for (int idx = t; idx < 4608; idx += 256) {
            int o = idx / 72, r = idx - o * 72;
            int s = r >> 3, p = r & 7;
            const float* wp = wt + ((size_t)(obase + o) * CIN + c0 * 16 + p) * 9 + s;
            w2[o * 76 + s * 8 + p] = bfsplit2(__ldg(wp), __ldg(wp + 72));
        }
        __syncthreads();

#pragma unroll
        for (int ky = 0; ky < 3; ++ky) {
#pragma unroll
            for (int kx = 0; kx < 3; ++kx) {
                const int s = ky * 3 + kx;
                const uint2* pw = w2 + (mwarp * 16 + g) * 76 + s * 8 + tg;
                uint2 A0 = pw[0];
                uint2 A2 = pw[4];
                uint2 A1 = pw[8 * 76];
                uint2 A3 = pw[8 * 76 + 4];
                const int fb = tg * PX3 + ky * 130 + nwarp * 64 + g + kx;
#pragma unroll
                for (int nt = 0; nt < 8; ++nt) {
                    uint2 B0 = x2[fb + nt * 8];
                    uint2 B1 = x2[fb + 4 * PX3 + nt * 8];
                    mma_bf16(acc[nt], A0.x, A1.x, A2.x, A3.x, B0.x, B1.x);
                    mma_bf16(acc[nt], A0.y, A1.y, A2.y, A3.y, B0.x, B1.x);
                    mma_bf16(acc[nt], A0.x, A1.x, A2.x, A3.x, B0.y, B1.y);
                }
            }
        }
    }

    const int o_lo = obase + mwarp * 16 + g;
    const float b_lo = __ldg(bias + o_lo);
    const float b_hi = __ldg(bias + o_lo + 8);
    float* row_lo = out + ((size_t)o_lo * H + y) * W;
    float* row_hi = out + ((size_t)(o_lo + 8) * H + y) * W;
#pragma unroll
    for (int nt = 0; nt < 8; ++nt) {
        int x = x0 + nwarp * 64 + nt * 8 + 2 * tg;
        float2 v0 = make_float2(fmaxf(acc[nt][0] + b_lo, 0.f),
                                fmaxf(acc[nt][1] + b_lo, 0.f));
        float2 v1 = make_float2(fmaxf(acc[nt][2] + b_hi, 0.f),
                                fmaxf(acc[nt][3] + b_hi, 0.f));
        *reinterpret_cast<float2*>(row_lo + x) = v0;
        *reinterpret_cast<float2*>(row_hi + x) = v1;
    }
}

// ---------------- global average pool: 128 channels of 256x256 ----------------
__global__ void avgpool_kernel(const float* __restrict__ in, float* __restrict__ feat) {
    const int c = blockIdx.x;
    const float* p = in + (size_t)c * 65536;
    float s = 0.f;
    for (int i = threadIdx.x; i < 65536; i += 256) s += p[i];
    __shared__ float sh[256];
    sh[threadIdx.x] = s;
    __syncthreads();
    for (int off = 128; off > 0; off >>= 1) {
        if (threadIdx.x < off) sh[threadIdx.x] += sh[threadIdx.x + off];
        __syncthreads();
    }
    if (threadIdx.x == 0) feat[c] = sh[0] * (1.f / 65536.f);
}

// ---------------- fused small FC trunk + s head (softplus+sort); exports f2 ----------
__device__ __forceinline__ float dot4(const float* __restrict__ w,
                                      const float* __restrict__ v, int n4) {
    float a = 0.f;
    const float4* w4 = (const float4*)w;
    const float4* v4 = (const float4*)v;
#pragma unroll 8
    for (int k = 0; k < n4; ++k) {
        float4 ww = w4[k], vv = v4[k];
        a += ww.x * vv.x + ww.y * vv.y + ww.z * vv.z + ww.w * vv.w;
    }
    return a;
}

__global__ __launch_bounds__(512)
void small_layers_kernel(const float* __restrict__ feat,
    const float* __restrict__ fw1, const float* __restrict__ fb1,
    const float* __restrict__ fw2, const float* __restrict__ fb2,
    const float* __restrict__ sw1, const float* __restrict__ sb1,
    const float* __restrict__ sw2, const float* __restrict__ sb2,
    float* __restrict__ f2g, float* __restrict__ s_out) {
    __shared__ __align__(16) float sf[128];
    __shared__ __align__(16) float f1[256];
    __shared__ __align__(16) float f2[512];
    __shared__ __align__(16) float s1[256];
    __shared__ float sv[128];
    const int t = threadIdx.x;

    if (t < 128) sf[t] = feat[t];
    __syncthreads();

    if (t < 256) f1[t] = fmaxf(fb1[t] + dot4(fw1 + t * 128, sf, 32), 0.f);
    __syncthreads();

    {
        float val = fmaxf(fb2[t] + dot4(fw2 + t * 256, f1, 64), 0.f);
        f2[t] = val;
        f2g[t] = val;
    }
    __syncthreads();

    if (t < 256) s1[t] = fmaxf(sb1[t] + dot4(sw1 + (size_t)t * 512, f2, 128), 0.f);
    __syncthreads();

    if (t < 128) {
        float xv = sb2[t] + dot4(sw2 + t * 256, s1, 64);
        sv[t] = (xv > 0.f) ? (xv + log1pf(expf(-xv))) : log1pf(expf(xv));
    }
    __syncthreads();

    if (t < 128) {
        float v = sv[t];
        int rank = 0;
        for (int j = 0; j < 128; ++j) {
            float o = sv[j];
            rank += (o > v) || (o == v && j > t);
        }
        s_out[rank] = v;
    }
}

// ---------------- u1/v1 matvecs in parallel (1024 warps) ----------------
__global__ __launch_bounds__(256)
void u1v1_kernel(const float* __restrict__ uw1, const float* __restrict__ ub1,
                 const float* __restrict__ vw1, const float* __restrict__ vb1,
                 const float* __restrict__ f2g,
                 float* __restrict__ u1, float* __restrict__ v1) {
    __shared__ __align__(16) float sf[512];
    const int t = threadIdx.x;
    sf[t] = f2g[t]; sf[t + 256] = f2g[t + 256];
    __syncthreads();
    const int lane = t & 31, warp = t >> 5;
    const int row = blockIdx.x * 8 + warp;          // 0..1023
    const float* wrow;
    float b; float* dst;
    if (row < 512) { wrow = uw1 + (size_t)row * 512; b = ub1[row]; dst = u1 + row; }
    else { wrow = vw1 + (size_t)(row - 512) * 512; b = vb1[row - 512]; dst = v1 + (row - 512); }
    float a = 0.f;
    const float4* w4 = (const float4*)wrow;
    const float4* x4 = (const float4*)sf;
#pragma unroll
    for (int k = lane; k < 128; k += 32) {
        float4 ww = w4[k], vv = x4[k];
        a += ww.x * vv.x + ww.y * vv.y + ww.z * vv.z + ww.w * vv.w;
    }
#pragma unroll
    for (int off = 16; off; off >>= 1) a += __shfl_down_sync(0xffffffffu, a, off);
    if (lane == 0) *dst = fmaxf(a + b, 0.f);
}

// ---------------- big head matvecs: 2 x (131072 x 512), write transposed ----------------
__global__ __launch_bounds__(256)
void big_head_kernel(const float* __restrict__ uw2, const float* __restrict__ ub2,
                     const float* __restrict__ vw2, const float* __restrict__ vb2,
                     const float* __restrict__ u1, const float* __restrict__ v1,
                     float* __restrict__ Ut, float* __restrict__ Vt) {
    __shared__ __align__(16) float su[512];
    __shared__ __align__(16) float svv[512];
    const int t = threadIdx.x;
    for (int i = t; i < 512; i += 256) { su[i] = u1[i]; svv[i] = v1[i]; }
    __syncthreads();

    const int lane = t & 31, warp = t >> 5;
    const int gw = blockIdx.x * 8 + warp;
#pragma unroll 1
    for (int rr = 0; rr < 16; ++rr) {
        int e = gw * 16 + rr;
        const float* wrow; const float* xv; float b; float* dst;
        if (e < 131072) {
            wrow = uw2 + (size_t)e * 512; xv = su; b = ub2[e];
            int m = e >> 8, r = (e >> 1) & 127, cp = e & 1;
            dst = Ut + (size_t)(r * 512 + m) * 2 + cp;
        } else {
            int e2 = e - 131072;
            wrow = vw2 + (size_t)e2 * 512; xv = svv; b = vb2[e2];
            int m = e2 >> 8, r = (e2 >> 1) & 127, cp = e2 & 1;
            dst = Vt + (size_t)(r * 512 + m) * 2 + cp;
        }
        float a = 0.f;
        const float4* w4 = (const float4*)wrow;
        const float4* x4 = (const float4*)xv;
#pragma unroll
        for (int k = lane; k < 128; k += 32) {
            float4 ww = w4[k], vv = x4[k];
            a += ww.x * vv.x + ww.y * vv.y + ww.z * vv.z + ww.w * vv.w;
        }
#pragma unroll
        for (int off = 16; off; off >>= 1) a += __shfl_down_sync(0xffffffffu, a, off);
        if (lane == 0) *dst = a + b;
    }
}

// ---------------- Gram: G = A^H A (FULL matrix) ------------------------------------
__global__ __launch_bounds__(256)
void gram_kernel(const float2* __restrict__ A0, const float2* __restrict__ A1,
                 float2* __restrict__ G) {
    const float2* A = (blockIdx.y == 0) ? A0 : A1;
    float2* Gm = G + blockIdx.y * 128 * 128;
    const int p = blockIdx.x;
    const int lane = threadIdx.x & 31, warp = threadIdx.x >> 5;
    const float2* ap = A + (size_t)p * 512;
    for (int q = warp; q < 128; q += 8) {
        const float2* aq = A + (size_t)q * 512;
        float cr = 0.f, ci = 0.f;
#pragma unroll
        for (int k = 0; k < 16; ++k) {
            float2 xp = ap[lane + 32 * k], xq = aq[lane + 32 * k];
            cr += xp.x * xq.x + xp.y * xq.y;    // re(conj(a_p) . a_q)
            ci += xp.x * xq.y - xp.y * xq.x;    // im
        }
#pragma unroll
        for (int off = 16; off; off >>= 1) {
            cr += __shfl_xor_sync(0xffffffffu, cr, off);
            ci += __shfl_xor_sync(0xffffffffu, ci, off);
        }
        if (lane == 0) Gm[p * 128 + q] = make_float2(cr, ci);
    }
}

// ---------------- Gram-space MGS with eps (EXACT reference semantics) --------------
#define GSG_SMEM_BYTES (128 * 130 * 8 + 2 * 128 * 8)
__global__ __launch_bounds__(1024, 1)
void gsgram_kernel(const float2* __restrict__ G, float2* __restrict__ gW) {
    extern __shared__ float2 sm2[];
    float2* sU  = sm2;                 // [col][row], col stride 130
    float2* sT  = sm2 + 128 * 130;     // t_i broadcast
    float2* sGT = sT + 128;            // (G t_i) broadcast
    const float2* Gm = G + blockIdx.x * 128 * 128;
    float2* Wm = gW + blockIdx.x * 128 * 128;
    const int t = threadIdx.x, lane = t & 31, warp = t >> 5;

    for (int idx = t; idx < 16384; idx += 1024) {
        int r = idx >> 7, j = idx & 127;
        sU[j * 130 + r] = Gm[r * 128 + j];
    }

    float2 v[4][4];                                // [colslot][rowslot]
#pragma unroll
    for (int cs = 0; cs < 4; ++cs)
#pragma unroll
        for (int rs = 0; rs < 4; ++rs) v[cs][rs] = make_float2(0.f, 0.f);
    if (lane == warp) {
#pragma unroll
        for (int cs = 0; cs < 4; ++cs) v[cs][cs] = make_float2(1.f, 0.f);
    }
    __syncthreads();

#pragma unroll 1
    for (int i = 0; i < 128; ++i) {
        const int iw = i & 31, is = i >> 5;
        if (warp == iw) {
            float d2 = 0.f;
#pragma unroll
            for (int rs = 0; rs < 4; ++rs) {
                float2 vv = v[is][rs];
                float2 uu = sU[i * 130 + lane + 32 * rs];
                d2 += vv.x * uu.x + vv.y * uu.y;
            }
#pragma unroll
            for (int off = 16; off; off >>= 1) d2 += __shfl_xor_sync(0xffffffffu, d2, off);
            const float inv = 1.f / sqrtf(d2 + 1e-8f);   // reference epsilon, exactly
#pragma unroll
            for (int rs = 0; rs < 4; ++rs) {
                int r = lane + 32 * rs;
                float2 vv = v[is][rs];
                float2 tv = make_float2(vv.x * inv, vv.y * inv);
                sT[r] = tv;
                Wm[i * 128 + r] = tv;
                float2 uu = sU[i * 130 + r];
                sGT[r] = make_float2(uu.x * inv, uu.y * inv);
            }
        }
        __syncthreads();
#pragma unroll
        for (int cs = 0; cs < 4; ++cs) {
            const int j = warp + 32 * cs;
            if (j > i) {
                float cr = 0.f, ci = 0.f;
#pragma unroll
                for (int rs = 0; rs < 4; ++rs) {
                    int r = lane + 32 * rs;
                    float2 tt = sT[r];
                    float2 uu = sU[j * 130 + r];
                    cr += tt.x * uu.x + tt.y * uu.y;
                    ci += tt.x * uu.y - tt.y * uu.x;
                }
#pragma unroll
                for (int off = 16; off; off >>= 1) {
                    cr += __shfl_xor_sync(0xffffffffu, cr, off);
                    ci += __shfl_xor_sync(0xffffffffu, ci, off);
                }
#pragma unroll
                for (int rs = 0; rs < 4; ++rs) {
                    int r = lane + 32 * rs;
                    float2 tt = sT[r];
                    v[cs][rs].x -= cr * tt.x - ci * tt.y;
                    v[cs][rs].y -= cr * tt.y + ci * tt.x;
                    float2 gg = sGT[r];
                    float2 uu = sU[j * 130 + r];
                    uu.x -= cr * gg.x - ci * gg.y;
                    uu.y -= cr * gg.y + ci * gg.x;
                    sU[j * 130 + r] = uu;
                }
            }
        }
        __syncthreads();
    }
}

// ---------------- apply: Q = A * W, write (m, r, 2) output layout -------------------
__global__ __launch_bounds__(256)
void apply_kernel(const float2* __restrict__ A0, const float2* __restrict__ A1,
                  const float2* __restrict__ gW, float* __restrict__ out) {
    const int mat = blockIdx.y;
    const float2* A = (mat == 0) ? A0 : A1;
    const float2* W = gW + mat * 128 * 128;
    float2* outp = (float2*)(out + ((mat == 0) ? 0 : (131072 + 128)));
    const int lane = threadIdx.x & 31, warp = threadIdx.x >> 5;
    const int j = blockIdx.x * 8 + warp;

    float2 acc[16];
#pragma unroll
    for (int s = 0; s < 16; ++s) acc[s] = make_float2(0.f, 0.f);

#pragma unroll 1
    for (int k = 0; k <= j; ++k) {                // t_j support: rows 0..j
        float2 w = __ldg(&W[j * 128 + k]);
        const float2* ak = A + (size_t)k * 512;
#pragma unroll
        for (int s = 0; s < 16; ++s) {
            float2 a = ak[lane + 32 * s];
            acc[s].x += w.x * a.x - w.y * a.y;
            acc[s].y += w.x * a.y + w.y * a.x;
        }
    }
#pragma unroll
    for (int s = 0; s < 16; ++s)
        outp[(size_t)(lane + 32 * s) * 128 + j] = acc[s];
}

// ---------------- launch ----------------
extern "C" void kernel_launch(void* const* d_in, const int* in_sizes, int n_in,
                              void* d_out, int out_size) {
    const float* x   = (const float*)d_in[0];
    const float* cw1 = (const float*)d_in[1];  const float* cb1 = (const float*)d_in[2];
    const float* cw2 = (const float*)d_in[3];  const float* cb2 = (const float*)d_in[4];
    const float* cw3 = (const float*)d_in[5];  const float* cb3 = (const float*)d_in[6];
    const float* fw1 = (const float*)d_in[7];  const float* fb1 = (const float*)d_in[8];
    const float* fw2 = (const float*)d_in[9];  const float* fb2 = (const float*)d_in[10];
    const float* sw1 = (const float*)d_in[11]; const float* sb1 = (const float*)d_in[12];
    const float* sw2 = (const float*)d_in[13]; const float* sb2 = (const float*)d_in[14];
    const float* uw1 = (const float*)d_in[15]; const float* ub1 = (const float*)d_in[16];
    const float* uw2 = (const float*)d_in[17]; const float* ub2 = (const float*)d_in[18];
    const float* vw1 = (const float*)d_in[19]; const float* vb1 = (const float*)d_in[20];
    const float* vw2 = (const float*)d_in[21]; const float* vb2 = (const float*)d_in[22];
    float* out = (float*)d_out;

    float *xchw, *h3, *feat, *f2g, *u1, *v1;
    uint2 *h1p, *h2pb;
    float2 *Ut, *Vt, *G, *W;
    cudaGetSymbolAddress((void**)&xchw, g_xchw);
    cudaGetSymbolAddress((void**)&h1p,  g_h1p);
    cudaGetSymbolAddress((void**)&h2pb, g_h2pb);
    cudaGetSymbolAddress((void**)&h3,   g_h3);
    cudaGetSymbolAddress((void**)&feat, g_feat);
    cudaGetSymbolAddress((void**)&f2g,  g_f2);
    cudaGetSymbolAddress((void**)&u1,   g_u1);
    cudaGetSymbolAddress((void**)&v1,   g_v1);
    cudaGetSymbolAddress((void**)&Ut,   g_Ut);
    cudaGetSymbolAddress((void**)&Vt,   g_Vt);
    cudaGetSymbolAddress((void**)&G,    g_G);
    cudaGetSymbolAddress((void**)&W,    g_W);

    const int gsg_smem = GSG_SMEM_BYTES;        // 135168 B
    cudaFuncSetAttribute(conv2_mma_pool, cudaFuncAttributeMaxDynamicSharedMemorySize,
                         C2P_SMEM_BYTES);
    cudaFuncSetAttribute(conv3x3_mma<64>, cudaFuncAttributeMaxDynamicSharedMemorySize,
                         CMM_SMEM_BYTES);
    cudaFuncSetAttribute(gsgram_kernel, cudaFuncAttributeMaxDynamicSharedMemorySize, gsg_smem);

    prep_x_kernel<<<1024, 256>>>(x, xchw);
    conv3x3_relu<2><<<dim3(2, 512, 2), 128, 16 * 2 * 9 * 4>>>(xchw, cw1, cb1, h1p, 512, 512);
    conv2_mma_pool<<<dim3(4, 256, 1), 256, C2P_SMEM_BYTES>>>(h1p, cw2, cb2, h2pb);
    conv3x3_mma<64><<<dim3(2, 256, 2), 256, CMM_SMEM_BYTES>>>(h2pb, cw3, cb3, h3, 256, 256);
    avgpool_kernel<<<128, 256>>>(h3, feat);
    small_layers_kernel<<<1, 512>>>(feat, fw1, fb1, fw2, fb2, sw1, sb1, sw2, sb2,
                                    f2g, out + 131072);
    u1v1_kernel<<<128, 256>>>(uw1, ub1, vw1, vb1, f2g, u1, v1);
    big_head_kernel<<<2048, 256>>>(uw2, ub2, vw2, vb2, u1, v1, (float*)Ut, (float*)Vt);

    gram_kernel<<<dim3(128, 2), 256>>>(Ut, Vt, G);
    gsgram_kernel<<<2, 1024, gsg_smem>>>(G, W);
    apply_kernel<<<dim3(16, 2), 256>>>(Ut, Vt, W, out);
}